// round 2
// baseline (speedup 1.0000x reference)
#include <cuda_runtime.h>
#include <cfloat>
#include <math.h>

#define Q 8192
#define S 4096
#define C 1024
#define WAY 64
#define KNN 5

// output layout: tuple flattened in return order (float32)
constexpr int OFF_CLS  = 0;                  // [Q,64]
constexpr int OFF_IDX  = Q * WAY;            // [Q,5]
constexpr int OFF_DIST = OFF_IDX + Q * KNN;  // [Q,5]
constexpr int OFF_PRED = OFF_DIST + Q * KNN; // [Q]
constexpr int OFF_SC   = OFF_PRED + Q;       // [Q,64]

// scratch (device globals: allocation-free)
__device__ float g_qn[Q * C];
__device__ float g_sn[S * C];
__device__ float g_protoT[C * WAY];   // k-major prototypes
__device__ float g_pval[Q * 4 * KNN]; // partial top5 values per s-split
__device__ int   g_pidx[Q * 4 * KNN];

typedef unsigned long long u64;

__device__ __forceinline__ u64 fma2(u64 a, u64 b, u64 c) {
    u64 d;
    asm("fma.rn.f32x2 %0, %1, %2, %3;" : "=l"(d) : "l"(a), "l"(b), "l"(c));
    return d;
}
__device__ __forceinline__ u64 pack2(float x) {
    u64 r;
    asm("mov.b64 %0, {%1, %1};" : "=l"(r) : "f"(x));
    return r;
}
__device__ __forceinline__ void unpack2(u64 v, float& lo, float& hi) {
    asm("mov.b64 {%0, %1}, %2;" : "=f"(lo), "=f"(hi) : "l"(v));
}

// jax.lax.top_k: larger value first; exact tie -> lower index first
__device__ __forceinline__ bool better(float x, int xi, float v, int vi) {
    return (x > v) || (x == v && xi < vi);
}
__device__ __forceinline__ void insert5(float* v, int* id, float x, int xi) {
    if (!better(x, xi, v[4], id[4])) return;
    bool b3 = better(x, xi, v[3], id[3]);
    bool b2 = better(x, xi, v[2], id[2]);
    bool b1 = better(x, xi, v[1], id[1]);
    bool b0 = better(x, xi, v[0], id[0]);
    v[4] = b3 ? v[3] : x; id[4] = b3 ? id[3] : xi;
    if (b3) { v[3] = b2 ? v[2] : x; id[3] = b2 ? id[2] : xi; }
    if (b2) { v[2] = b1 ? v[1] : x; id[2] = b1 ? id[1] : xi; }
    if (b1) { v[1] = b0 ? v[0] : x; id[1] = b0 ? id[0] : xi; }
    if (b0) { v[0] = x; id[0] = xi; }
}

// ============================================================
// 1) row L2-normalize: blocks [0,Q) -> queries, [Q,Q+S) -> supports
// ============================================================
__global__ void __launch_bounds__(256) normalize_kernel(const float* __restrict__ qimg,
                                                        const float* __restrict__ simg) {
    __shared__ float red[9];
    const int b = blockIdx.x, t = threadIdx.x;
    const float* src; float* dst;
    if (b < Q) { src = qimg + (size_t)b * C;       dst = g_qn + (size_t)b * C; }
    else       { src = simg + (size_t)(b - Q) * C; dst = g_sn + (size_t)(b - Q) * C; }
    float4 v = ((const float4*)src)[t];
    float ss = v.x * v.x + v.y * v.y + v.z * v.z + v.w * v.w;
#pragma unroll
    for (int o = 16; o > 0; o >>= 1) ss += __shfl_xor_sync(0xffffffffu, ss, o);
    if ((t & 31) == 0) red[t >> 5] = ss;
    __syncthreads();
    if (t == 0) {
        float s = 0.f;
#pragma unroll
        for (int i = 0; i < 8; i++) s += red[i];
        red[8] = fmaxf(sqrtf(s), 1e-12f);
    }
    __syncthreads();
    const float dn = red[8];
    float4 o; o.x = v.x / dn; o.y = v.y / dn; o.z = v.z / dn; o.w = v.w / dn;
    ((float4*)dst)[t] = o;
}

// ============================================================
// 2) prototypes: per-class mean of normalized supports + l2norm
//    one block per class (64 blocks x 256 threads), k-major output
// ============================================================
__global__ void __launch_bounds__(256) proto_kernel(const int* __restrict__ labels) {
    __shared__ int slab[S];
    __shared__ float red[9];
    const int w = blockIdx.x, t = threadIdx.x;
    for (int i = t; i < S; i += 256) slab[i] = labels[i];
    __syncthreads();
    float ax = 0.f, ay = 0.f, az = 0.f, aw = 0.f;
    int cnt = 0;
    for (int s = 0; s < S; s++) {
        if (slab[s] == w) {
            float4 v = ((const float4*)(g_sn + (size_t)s * C))[t];
            ax += v.x; ay += v.y; az += v.z; aw += v.w; cnt++;
        }
    }
    const float fc = (float)(cnt > 0 ? cnt : 1);
    ax /= fc; ay /= fc; az /= fc; aw /= fc;
    float ss = ax * ax + ay * ay + az * az + aw * aw;
#pragma unroll
    for (int o = 16; o > 0; o >>= 1) ss += __shfl_xor_sync(0xffffffffu, ss, o);
    if ((t & 31) == 0) red[t >> 5] = ss;
    __syncthreads();
    if (t == 0) {
        float s = 0.f;
#pragma unroll
        for (int i = 0; i < 8; i++) s += red[i];
        red[8] = fmaxf(sqrtf(s), 1e-12f);
    }
    __syncthreads();
    const float dn = red[8];
    const int c0 = t * 4;
    g_protoT[(c0 + 0) * WAY + w] = ax / dn;
    g_protoT[(c0 + 1) * WAY + w] = ay / dn;
    g_protoT[(c0 + 2) * WAY + w] = az / dn;
    g_protoT[(c0 + 3) * WAY + w] = aw / dn;
}

// ============================================================
// 3) sim GEMM + fused per-split top-5
//    grid (Q/128, 4 s-splits), 256 threads, 128x128 tile, BK=16, 8x8 micro
// ============================================================
#define BM 128
#define BN 128
#define BK 16
#define SPLIT_S 1024

__global__ void __launch_bounds__(256) sim_topk_kernel() {
    __shared__ __align__(16) float As[BK][BM];
    __shared__ __align__(16) float Bs[BK][BN];
    const int t = threadIdx.x;
    const int tx = t & 15, ty = t >> 4;
    const int qb = blockIdx.x * BM;
    const int split = blockIdx.y;
    const int sb0 = split * SPLIT_S;

    float tv[8][5]; int tidx[8][5];
#pragma unroll
    for (int i = 0; i < 8; i++)
#pragma unroll
        for (int r = 0; r < 5; r++) { tv[i][r] = -FLT_MAX; tidx[i][r] = 0x7fffffff; }

    for (int sub = 0; sub < SPLIT_S / BN; sub++) {
        const int sb = sb0 + sub * BN;
        u64 acc[8][4];
#pragma unroll
        for (int i = 0; i < 8; i++)
#pragma unroll
            for (int j = 0; j < 4; j++) acc[i][j] = 0ull;

        for (int kc = 0; kc < C; kc += BK) {
#pragma unroll
            for (int l = 0; l < 2; l++) {
                int f = t + (l << 8);
                int row = f >> 2, kq = (f & 3) << 2;
                float4 a = *(const float4*)(g_qn + (size_t)(qb + row) * C + kc + kq);
                float4 b = *(const float4*)(g_sn + (size_t)(sb + row) * C + kc + kq);
                As[kq + 0][row] = a.x; As[kq + 1][row] = a.y;
                As[kq + 2][row] = a.z; As[kq + 3][row] = a.w;
                Bs[kq + 0][row] = b.x; Bs[kq + 1][row] = b.y;
                Bs[kq + 2][row] = b.z; Bs[kq + 3][row] = b.w;
            }
            __syncthreads();
#pragma unroll
            for (int k = 0; k < BK; k++) {
                float4 a0 = *(const float4*)(&As[k][ty * 8]);
                float4 a1 = *(const float4*)(&As[k][ty * 8 + 4]);
                ulonglong2 b0 = *(const ulonglong2*)(&Bs[k][tx * 8]);
                ulonglong2 b1 = *(const ulonglong2*)(&Bs[k][tx * 8 + 4]);
                u64 bv0 = b0.x, bv1 = b0.y, bv2 = b1.x, bv3 = b1.y;
                u64 ap[8];
                ap[0] = pack2(a0.x); ap[1] = pack2(a0.y); ap[2] = pack2(a0.z); ap[3] = pack2(a0.w);
                ap[4] = pack2(a1.x); ap[5] = pack2(a1.y); ap[6] = pack2(a1.z); ap[7] = pack2(a1.w);
#pragma unroll
                for (int i = 0; i < 8; i++) {
                    acc[i][0] = fma2(ap[i], bv0, acc[i][0]);
                    acc[i][1] = fma2(ap[i], bv1, acc[i][1]);
                    acc[i][2] = fma2(ap[i], bv2, acc[i][2]);
                    acc[i][3] = fma2(ap[i], bv3, acc[i][3]);
                }
            }
            __syncthreads();
        }
        // fold this 128-support subtile into the per-thread top5
#pragma unroll
        for (int i = 0; i < 8; i++)
#pragma unroll
            for (int j = 0; j < 4; j++) {
                float lo, hi; unpack2(acc[i][j], lo, hi);
                insert5(tv[i], tidx[i], lo, sb + tx * 8 + 2 * j);
                insert5(tv[i], tidx[i], hi, sb + tx * 8 + 2 * j + 1);
            }
    }

    // butterfly merge across the 16 tx lanes sharing each ty (contiguous half-warps)
#pragma unroll
    for (int off = 1; off < 16; off <<= 1) {
#pragma unroll
        for (int i = 0; i < 8; i++) {
            float ov[5]; int oi[5];
#pragma unroll
            for (int r = 0; r < 5; r++) {
                ov[r] = __shfl_xor_sync(0xffffffffu, tv[i][r], off);
                oi[r] = __shfl_xor_sync(0xffffffffu, tidx[i][r], off);
            }
#pragma unroll
            for (int r = 0; r < 5; r++) insert5(tv[i], tidx[i], ov[r], oi[r]);
        }
    }

    if (tx == 0) {
#pragma unroll
        for (int i = 0; i < 8; i++) {
            int q = qb + ty * 8 + i;
#pragma unroll
            for (int r = 0; r < 5; r++) {
                g_pval[(q * 4 + split) * 5 + r] = tv[i][r];
                g_pidx[(q * 4 + split) * 5 + r] = tidx[i][r];
            }
        }
    }
}

// ============================================================
// 4) merge 4 split-partials per query + vote + emit idx/dist/pred
// ============================================================
__global__ void __launch_bounds__(256) merge_vote_kernel(const int* __restrict__ labels,
                                                         float* __restrict__ out) {
    const int q = blockIdx.x * 256 + threadIdx.x;
    float v[5]; int id[5];
#pragma unroll
    for (int r = 0; r < 5; r++) { v[r] = -FLT_MAX; id[r] = 0x7fffffff; }
    for (int sp = 0; sp < 4; sp++)
#pragma unroll
        for (int r = 0; r < 5; r++)
            insert5(v, id, g_pval[(q * 4 + sp) * 5 + r], g_pidx[(q * 4 + sp) * 5 + r]);
#pragma unroll
    for (int r = 0; r < 5; r++) {
        out[OFF_IDX + q * 5 + r] = (float)id[r];
        out[OFF_DIST + q * 5 + r] = 1.0f - v[r];
    }
    int lab[5];
#pragma unroll
    for (int r = 0; r < 5; r++) lab[r] = labels[id[r]];
    int bestc = 0, bestl = 1 << 30;
#pragma unroll
    for (int r = 0; r < 5; r++) {
        int c = 0;
#pragma unroll
        for (int j = 0; j < 5; j++) c += (lab[j] == lab[r]);
        if (c > bestc || (c == bestc && lab[r] < bestl)) { bestc = c; bestl = lab[r]; }
    }
    out[OFF_PRED + q] = (float)bestl;
}

// ============================================================
// 5) scores = q_norm @ protoT -> classification_scores (10x) + scores
//    grid 128 blocks, 64q x 64w tile, BK=16, 4x4 micro
// ============================================================
__global__ void __launch_bounds__(256) scores_kernel(float* __restrict__ out) {
    __shared__ __align__(16) float Aq[16][64];
    __shared__ __align__(16) float Bp[16][64];
    const int t = threadIdx.x;
    const int tx = t & 15, ty = t >> 4;
    const int qb = blockIdx.x * 64;
    float acc[4][4];
#pragma unroll
    for (int i = 0; i < 4; i++)
#pragma unroll
        for (int j = 0; j < 4; j++) acc[i][j] = 0.f;

    const int arow = t >> 2, akq = (t & 3) << 2;
    const int bkr = t >> 4, bwq = (t & 15) << 2;
    for (int kc = 0; kc < C; kc += 16) {
        float4 a = *(const float4*)(g_qn + (size_t)(qb + arow) * C + kc + akq);
        Aq[akq + 0][arow] = a.x; Aq[akq + 1][arow] = a.y;
        Aq[akq + 2][arow] = a.z; Aq[akq + 3][arow] = a.w;
        *(float4*)(&Bp[bkr][bwq]) = *(const float4*)(g_protoT + (size_t)(kc + bkr) * WAY + bwq);
        __syncthreads();
#pragma unroll
        for (int k = 0; k < 16; k++) {
            float4 av = *(const float4*)(&Aq[k][ty * 4]);
            float4 bv = *(const float4*)(&Bp[k][tx * 4]);
            float aa[4] = {av.x, av.y, av.z, av.w};
            float bb[4] = {bv.x, bv.y, bv.z, bv.w};
#pragma unroll
            for (int i = 0; i < 4; i++)
#pragma unroll
                for (int j = 0; j < 4; j++) acc[i][j] = fmaf(aa[i], bb[j], acc[i][j]);
        }
        __syncthreads();
    }
#pragma unroll
    for (int i = 0; i < 4; i++) {
        int q = qb + ty * 4 + i;
#pragma unroll
        for (int j = 0; j < 4; j++) {
            int w = tx * 4 + j;
            float s = acc[i][j];
            out[OFF_SC + (size_t)q * WAY + w] = s;
            out[OFF_CLS + (size_t)q * WAY + w] = 10.0f * s;
        }
    }
}

extern "C" void kernel_launch(void* const* d_in, const int* in_sizes, int n_in,
                              void* d_out, int out_size) {
    const float* simg   = (const float*)d_in[0];  // [4096,1024]
    const int*   labels = (const int*)d_in[1];    // [4096]
    const float* qimg   = (const float*)d_in[2];  // [8192,1024]
    float* out = (float*)d_out;

    normalize_kernel<<<Q + S, 256>>>(qimg, simg);
    proto_kernel<<<WAY, 256>>>(labels);
    sim_topk_kernel<<<dim3(Q / BM, 4), 256>>>();
    merge_vote_kernel<<<Q / 256, 256>>>(labels, out);
    scores_kernel<<<Q / 64, 256>>>(out);
}

// round 4
// speedup vs baseline: 3.4160x; 3.4160x over previous
#include <cuda_runtime.h>
#include <cuda_bf16.h>
#include <cstdint>
#include <cfloat>
#include <math.h>

#define Q 8192
#define S 4096
#define C 1024
#define WAY 64
#define KNN 5

// output layout: tuple flattened in return order (float32)
constexpr int OFF_CLS  = 0;                  // [Q,64]
constexpr int OFF_IDX  = Q * WAY;            // [Q,5]
constexpr int OFF_DIST = OFF_IDX + Q * KNN;  // [Q,5]
constexpr int OFF_PRED = OFF_DIST + Q * KNN; // [Q]
constexpr int OFF_SC   = OFF_PRED + Q;       // [Q,64]

#define SPLITS 8      // s-splits of 512 supports
#define TOPC 5        // exact-bf16 top-5 kept per (query, split)
#define RESC 10       // candidates rescored exactly per query
#define RS 80         // smem row stride bytes (64B data + 16B pad)

// scratch (device globals: allocation-free)
__device__ float          g_qn[Q * C];
__device__ float          g_sn[S * C];
__device__ __nv_bfloat16  g_qb[Q * C];
__device__ __nv_bfloat16  g_sb[S * C];
__device__ float          g_protoT[C * WAY];
__device__ float          g_pval[Q * SPLITS * TOPC];
__device__ int            g_pidx[Q * SPLITS * TOPC];

__device__ __forceinline__ uint32_t smem_to_u32(const void* p) {
    uint32_t a;
    asm("{ .reg .u64 t; cvta.to.shared.u64 t, %1; cvt.u32.u64 %0, t; }" : "=r"(a) : "l"(p));
    return a;
}
#define LDSM_X4(r0, r1, r2, r3, addr) \
    asm volatile("ldmatrix.sync.aligned.m8n8.x4.shared.b16 {%0,%1,%2,%3}, [%4];" \
                 : "=r"(r0), "=r"(r1), "=r"(r2), "=r"(r3) : "r"(addr))
#define MMA_BF16(c, a, b) \
    asm volatile("mma.sync.aligned.m16n8k16.row.col.f32.bf16.bf16.f32 " \
                 "{%0,%1,%2,%3}, {%4,%5,%6,%7}, {%8,%9}, {%0,%1,%2,%3};" \
                 : "+f"((c)[0]), "+f"((c)[1]), "+f"((c)[2]), "+f"((c)[3]) \
                 : "r"((a)[0]), "r"((a)[1]), "r"((a)[2]), "r"((a)[3]), "r"((b)[0]), "r"((b)[1]))

// jax.lax.top_k tie rule: larger value first; exact tie -> lower index first
__device__ __forceinline__ bool better(float x, int xi, float v, int vi) {
    return (x > v) || (x == v && xi < vi);
}
template <int K>
__device__ __forceinline__ void insertK(float* v, int* id, float x, int xi) {
    if (!better(x, xi, v[K - 1], id[K - 1])) return;
    bool b[K];
#pragma unroll
    for (int r = 0; r < K; r++) b[r] = better(x, xi, v[r], id[r]);
#pragma unroll
    for (int r = K - 1; r > 0; r--) {
        v[r]  = b[r - 1] ? v[r - 1]  : (b[r] ? x  : v[r]);
        id[r] = b[r - 1] ? id[r - 1] : (b[r] ? xi : id[r]);
    }
    if (b[0]) { v[0] = x; id[0] = xi; }
}

// ============================================================
// 1) row L2-normalize + bf16 copies
// ============================================================
__global__ void __launch_bounds__(256) normalize_kernel(const float* __restrict__ qimg,
                                                        const float* __restrict__ simg) {
    __shared__ float red[9];
    const int b = blockIdx.x, t = threadIdx.x;
    const float* src; float* dst; __nv_bfloat16* bdst;
    if (b < Q) { src = qimg + (size_t)b * C;       dst = g_qn + (size_t)b * C; bdst = g_qb + (size_t)b * C; }
    else       { src = simg + (size_t)(b - Q) * C; dst = g_sn + (size_t)(b - Q) * C; bdst = g_sb + (size_t)(b - Q) * C; }
    float4 v = ((const float4*)src)[t];
    float ss = v.x * v.x + v.y * v.y + v.z * v.z + v.w * v.w;
#pragma unroll
    for (int o = 16; o > 0; o >>= 1) ss += __shfl_xor_sync(0xffffffffu, ss, o);
    if ((t & 31) == 0) red[t >> 5] = ss;
    __syncthreads();
    if (t == 0) {
        float s = 0.f;
#pragma unroll
        for (int i = 0; i < 8; i++) s += red[i];
        red[8] = fmaxf(sqrtf(s), 1e-12f);
    }
    __syncthreads();
    const float dn = red[8];
    float4 o; o.x = v.x / dn; o.y = v.y / dn; o.z = v.z / dn; o.w = v.w / dn;
    ((float4*)dst)[t] = o;
    __nv_bfloat162 b0, b1;
    b0.x = __float2bfloat16(o.x); b0.y = __float2bfloat16(o.y);
    b1.x = __float2bfloat16(o.z); b1.y = __float2bfloat16(o.w);
    ((__nv_bfloat162*)bdst)[t * 2]     = b0;
    ((__nv_bfloat162*)bdst)[t * 2 + 1] = b1;
}

// ============================================================
// 2) prototypes (per-class mean of normalized supports + l2norm)
// ============================================================
__global__ void __launch_bounds__(256) proto_kernel(const int* __restrict__ labels) {
    __shared__ int slab[S];
    __shared__ float red[9];
    const int w = blockIdx.x, t = threadIdx.x;
    for (int i = t; i < S; i += 256) slab[i] = labels[i];
    __syncthreads();
    float ax = 0.f, ay = 0.f, az = 0.f, aw = 0.f;
    int cnt = 0;
    for (int s = 0; s < S; s++) {
        if (slab[s] == w) {
            float4 v = ((const float4*)(g_sn + (size_t)s * C))[t];
            ax += v.x; ay += v.y; az += v.z; aw += v.w; cnt++;
        }
    }
    const float fc = (float)(cnt > 0 ? cnt : 1);
    ax /= fc; ay /= fc; az /= fc; aw /= fc;
    float ss = ax * ax + ay * ay + az * az + aw * aw;
#pragma unroll
    for (int o = 16; o > 0; o >>= 1) ss += __shfl_xor_sync(0xffffffffu, ss, o);
    if ((t & 31) == 0) red[t >> 5] = ss;
    __syncthreads();
    if (t == 0) {
        float s = 0.f;
#pragma unroll
        for (int i = 0; i < 8; i++) s += red[i];
        red[8] = fmaxf(sqrtf(s), 1e-12f);
    }
    __syncthreads();
    const float dn = red[8];
    const int c0 = t * 4;
    g_protoT[(c0 + 0) * WAY + w] = ax / dn;
    g_protoT[(c0 + 1) * WAY + w] = ay / dn;
    g_protoT[(c0 + 2) * WAY + w] = az / dn;
    g_protoT[(c0 + 3) * WAY + w] = aw / dn;
}

// ============================================================
// 3) HMMA bf16 sim GEMM + fused exact-bf16 top-5 per split
//    grid (64 q-tiles, 8 s-splits), 256 threads (warps 4m x 2n)
// ============================================================
__global__ void __launch_bounds__(256, 1) sim_topk_kernel() {
    __shared__ __align__(16) unsigned char sA[2][128 * RS];
    __shared__ __align__(16) unsigned char sB[2][128 * RS];
    __shared__ float dv[128][TOPC];
    __shared__ int   di[128][TOPC];

    const int t = threadIdx.x;
    const int lane = t & 31, wid = t >> 5;
    const int warp_m = wid & 3, warp_n = wid >> 2;
    const int qb = blockIdx.x * 128;
    const int split = blockIdx.y;
    const uint32_t aB0 = smem_to_u32(sA[0]), aB1 = smem_to_u32(sA[1]);
    const uint32_t bB0 = smem_to_u32(sB[0]), bB1 = smem_to_u32(sB[1]);

    // g2s indices: thread handles rows r0 and r0+64, 16B segment s0
    const int r0 = t >> 2, s0 = t & 3;
    const uint4* gq = (const uint4*)g_qb;  // 128 uint4 per row
    const uint4* gs = (const uint4*)g_sb;

    // ldmatrix byte offsets (fixed per thread per buffer)
    const int aoff0 = (warp_m * 32 + (lane & 15)) * RS + (lane >> 4) * 16;        // +mf*16*RS +ks*32
    const int boffN = (warp_n * 64 + (lane & 7) + ((lane & 16) ? 8 : 0)) * RS + ((lane >> 3) & 1) * 16;

    float tv[4][TOPC]; int ti[4][TOPC];
#pragma unroll
    for (int s = 0; s < 4; s++)
#pragma unroll
        for (int r = 0; r < TOPC; r++) { tv[s][r] = -FLT_MAX; ti[s][r] = 0x7fffffff; }

    for (int st = 0; st < 4; st++) {
        const int sr = split * 512 + st * 128;
        float c[2][8][4];
#pragma unroll
        for (int mf = 0; mf < 2; mf++)
#pragma unroll
            for (int nf = 0; nf < 8; nf++)
#pragma unroll
                for (int k = 0; k < 4; k++) c[mf][nf][k] = 0.f;

        // chunk 0 direct load
        {
            uint4 va0 = gq[(size_t)(qb + r0) * 128 + s0];
            uint4 va1 = gq[(size_t)(qb + r0 + 64) * 128 + s0];
            uint4 vb0 = gs[(size_t)(sr + r0) * 128 + s0];
            uint4 vb1 = gs[(size_t)(sr + r0 + 64) * 128 + s0];
            *(uint4*)(sA[0] + r0 * RS + s0 * 16) = va0;
            *(uint4*)(sA[0] + (r0 + 64) * RS + s0 * 16) = va1;
            *(uint4*)(sB[0] + r0 * RS + s0 * 16) = vb0;
            *(uint4*)(sB[0] + (r0 + 64) * RS + s0 * 16) = vb1;
        }
        __syncthreads();

        for (int cc = 0; cc < 32; cc++) {
            const int buf = cc & 1;
            uint4 pa0, pa1, pb0, pb1;
            if (cc < 31) {
                const int ci = (cc + 1) * 4 + s0;
                pa0 = gq[(size_t)(qb + r0) * 128 + ci];
                pa1 = gq[(size_t)(qb + r0 + 64) * 128 + ci];
                pb0 = gs[(size_t)(sr + r0) * 128 + ci];
                pb1 = gs[(size_t)(sr + r0 + 64) * 128 + ci];
            }
            const uint32_t ab = buf ? aB1 : aB0;
            const uint32_t bb = buf ? bB1 : bB0;
#pragma unroll
            for (int ks = 0; ks < 2; ks++) {
                uint32_t af[2][4], bf[8][2];
#pragma unroll
                for (int mf = 0; mf < 2; mf++)
                    LDSM_X4(af[mf][0], af[mf][1], af[mf][2], af[mf][3],
                            ab + aoff0 + mf * 16 * RS + ks * 32);
#pragma unroll
                for (int np = 0; np < 4; np++)
                    LDSM_X4(bf[np * 2][0], bf[np * 2][1], bf[np * 2 + 1][0], bf[np * 2 + 1][1],
                            bb + boffN + np * 16 * RS + ks * 32);
#pragma unroll
                for (int mf = 0; mf < 2; mf++)
#pragma unroll
                    for (int nf = 0; nf < 8; nf++)
                        MMA_BF16(c[mf][nf], af[mf], bf[nf]);
            }
            if (cc < 31) {
                unsigned char* dA = sA[buf ^ 1];
                unsigned char* dB = sB[buf ^ 1];
                *(uint4*)(dA + r0 * RS + s0 * 16) = pa0;
                *(uint4*)(dA + (r0 + 64) * RS + s0 * 16) = pa1;
                *(uint4*)(dB + r0 * RS + s0 * 16) = pb0;
                *(uint4*)(dB + (r0 + 64) * RS + s0 * 16) = pb1;
            }
            __syncthreads();
        }

        // fold this 128-support subtile into per-thread top-5 lists
#pragma unroll
        for (int mf = 0; mf < 2; mf++)
#pragma unroll
            for (int nf = 0; nf < 8; nf++) {
                const int colb = sr + warp_n * 64 + nf * 8 + (lane & 3) * 2;
                insertK<TOPC>(tv[mf * 2], ti[mf * 2], c[mf][nf][0], colb);
                insertK<TOPC>(tv[mf * 2], ti[mf * 2], c[mf][nf][1], colb + 1);
                insertK<TOPC>(tv[mf * 2 + 1], ti[mf * 2 + 1], c[mf][nf][2], colb);
                insertK<TOPC>(tv[mf * 2 + 1], ti[mf * 2 + 1], c[mf][nf][3], colb + 1);
            }
    }

    // quad merge (lanes sharing the same rows differ only in lane&3)
#pragma unroll
    for (int off = 1; off < 4; off <<= 1) {
#pragma unroll
        for (int s = 0; s < 4; s++) {
            float ov[TOPC]; int oi[TOPC];
#pragma unroll
            for (int r = 0; r < TOPC; r++) {
                ov[r] = __shfl_xor_sync(0xffffffffu, tv[s][r], off);
                oi[r] = __shfl_xor_sync(0xffffffffu, ti[s][r], off);
            }
#pragma unroll
            for (int r = 0; r < TOPC; r++) insertK<TOPC>(tv[s], ti[s], ov[r], oi[r]);
        }
    }

    // cross-warp_n merge via smem, then write per-(query, split) partial top-5
    const int g = lane >> 2;
    if (warp_n == 1 && (lane & 3) == 0) {
#pragma unroll
        for (int s = 0; s < 4; s++) {
            const int row = warp_m * 32 + (s >> 1) * 16 + (s & 1) * 8 + g;
#pragma unroll
            for (int r = 0; r < TOPC; r++) { dv[row][r] = tv[s][r]; di[row][r] = ti[s][r]; }
        }
    }
    __syncthreads();
    if (warp_n == 0 && (lane & 3) == 0) {
#pragma unroll
        for (int s = 0; s < 4; s++) {
            const int row = warp_m * 32 + (s >> 1) * 16 + (s & 1) * 8 + g;
#pragma unroll
            for (int r = 0; r < TOPC; r++) insertK<TOPC>(tv[s], ti[s], dv[row][r], di[row][r]);
            const size_t base = ((size_t)(qb + row) * SPLITS + split) * TOPC;
#pragma unroll
            for (int r = 0; r < TOPC; r++) { g_pval[base + r] = tv[s][r]; g_pidx[base + r] = ti[s][r]; }
        }
    }
}

// ============================================================
// 4) merge partials, exact fp32 rescore top-10, emit idx/dist/pred
//    one warp per query
// ============================================================
#define NCAND (SPLITS * TOPC)  // 40
__global__ void __launch_bounds__(256) merge_rescore_kernel(const int* __restrict__ labels,
                                                            float* __restrict__ out) {
    __shared__ float sval[8][NCAND];
    __shared__ int   sidx[8][NCAND];
    __shared__ int   ssel[8][RESC];
    __shared__ float sres[8][RESC];
    const int t = threadIdx.x, wid = t >> 5, lid = t & 31;
    const int q = blockIdx.x * 8 + wid;

    for (int i = lid; i < NCAND; i += 32) {
        sval[wid][i] = g_pval[(size_t)q * NCAND + i];
        sidx[wid][i] = g_pidx[(size_t)q * NCAND + i];
    }
    __syncwarp();
    if (lid == 0) {
        float v[RESC]; int id[RESC];
#pragma unroll
        for (int r = 0; r < RESC; r++) { v[r] = -FLT_MAX; id[r] = 0x7fffffff; }
        for (int i = 0; i < NCAND; i++) insertK<RESC>(v, id, sval[wid][i], sidx[wid][i]);
#pragma unroll
        for (int r = 0; r < RESC; r++) ssel[wid][r] = id[r];
    }
    __syncwarp();

    float4 qv[8];
#pragma unroll
    for (int k = 0; k < 8; k++)
        qv[k] = *(const float4*)(g_qn + (size_t)q * C + k * 128 + lid * 4);

#pragma unroll 1
    for (int c = 0; c < RESC; c++) {
        const int si = ssel[wid][c];
        const float* srow = g_sn + (size_t)si * C;
        float acc = 0.f;
#pragma unroll
        for (int k = 0; k < 8; k++) {
            float4 sv = *(const float4*)(srow + k * 128 + lid * 4);
            acc = fmaf(qv[k].x, sv.x, acc);
            acc = fmaf(qv[k].y, sv.y, acc);
            acc = fmaf(qv[k].z, sv.z, acc);
            acc = fmaf(qv[k].w, sv.w, acc);
        }
#pragma unroll
        for (int o = 16; o > 0; o >>= 1) acc += __shfl_xor_sync(0xffffffffu, acc, o);
        if (lid == 0) sres[wid][c] = acc;
    }
    __syncwarp();

    if (lid == 0) {
        float v5[5]; int i5[5];
#pragma unroll
        for (int r = 0; r < 5; r++) { v5[r] = -FLT_MAX; i5[r] = 0x7fffffff; }
#pragma unroll
        for (int c = 0; c < RESC; c++) insertK<5>(v5, i5, sres[wid][c], ssel[wid][c]);
#pragma unroll
        for (int r = 0; r < 5; r++) {
            out[OFF_IDX + q * 5 + r] = (float)i5[r];
            out[OFF_DIST + q * 5 + r] = 1.0f - v5[r];
        }
        int lab[5];
#pragma unroll
        for (int r = 0; r < 5; r++) lab[r] = labels[i5[r]];
        int bestc = 0, bestl = 1 << 30;
#pragma unroll
        for (int r = 0; r < 5; r++) {
            int cn = 0;
#pragma unroll
            for (int j = 0; j < 5; j++) cn += (lab[j] == lab[r]);
            if (cn > bestc || (cn == bestc && lab[r] < bestl)) { bestc = cn; bestl = lab[r]; }
        }
        out[OFF_PRED + q] = (float)bestl;
    }
}

// ============================================================
// 5) scores = q_norm @ protoT -> classification_scores (10x) + scores
// ============================================================
__global__ void __launch_bounds__(256) scores_kernel(float* __restrict__ out) {
    __shared__ __align__(16) float Aq[16][64];
    __shared__ __align__(16) float Bp[16][64];
    const int t = threadIdx.x;
    const int tx = t & 15, ty = t >> 4;
    const int qb = blockIdx.x * 64;
    float acc[4][4];
#pragma unroll
    for (int i = 0; i < 4; i++)
#pragma unroll
        for (int j = 0; j < 4; j++) acc[i][j] = 0.f;

    const int arow = t >> 2, akq = (t & 3) << 2;
    const int bkr = t >> 4, bwq = (t & 15) << 2;
    for (int kc = 0; kc < C; kc += 16) {
        float4 a = *(const float4*)(g_qn + (size_t)(qb + arow) * C + kc + akq);
        Aq[akq + 0][arow] = a.x; Aq[akq + 1][arow] = a.y;
        Aq[akq + 2][arow] = a.z; Aq[akq + 3][arow] = a.w;
        *(float4*)(&Bp[bkr][bwq]) = *(const float4*)(g_protoT + (size_t)(kc + bkr) * WAY + bwq);
        __syncthreads();
#pragma unroll
        for (int k = 0; k < 16; k++) {
            float4 av = *(const float4*)(&Aq[k][ty * 4]);
            float4 bv = *(const float4*)(&Bp[k][tx * 4]);
            float aa[4] = {av.x, av.y, av.z, av.w};
            float bb[4] = {bv.x, bv.y, bv.z, bv.w};
#pragma unroll
            for (int i = 0; i < 4; i++)
#pragma unroll
                for (int j = 0; j < 4; j++) acc[i][j] = fmaf(aa[i], bb[j], acc[i][j]);
        }
        __syncthreads();
    }
#pragma unroll
    for (int i = 0; i < 4; i++) {
        int q = qb + ty * 4 + i;
#pragma unroll
        for (int j = 0; j < 4; j++) {
            int w = tx * 4 + j;
            float s = acc[i][j];
            out[OFF_SC + (size_t)q * WAY + w] = s;
            out[OFF_CLS + (size_t)q * WAY + w] = 10.0f * s;
        }
    }
}

extern "C" void kernel_launch(void* const* d_in, const int* in_sizes, int n_in,
                              void* d_out, int out_size) {
    const float* simg   = (const float*)d_in[0];
    const int*   labels = (const int*)d_in[1];
    const float* qimg   = (const float*)d_in[2];
    float* out = (float*)d_out;

    normalize_kernel<<<Q + S, 256>>>(qimg, simg);
    proto_kernel<<<WAY, 256>>>(labels);
    sim_topk_kernel<<<dim3(Q / 128, SPLITS), 256>>>();
    merge_rescore_kernel<<<Q / 8, 256>>>(labels, out);
    scores_kernel<<<Q / 64, 256>>>(out);
}